// round 2
// baseline (speedup 1.0000x reference)
#include <cuda_runtime.h>
#include <math.h>
#include <stdint.h>

#define H_DIM 4096
#define I_DIM 11008
#define M_DIM 8192

// Scratch for intermediate h = silu(x@wg) * (x@wu)   [M, I] fp32
__device__ float g_h[(size_t)M_DIM * I_DIM];

// ---------------------------------------------------------------------------
// Kernel 1: fused gate/up GEMM + SiLU*mul epilogue
// C tile 128x64, BK=16, 256 threads, per-thread 8x4 for each of gate & up.
// x:  [M, 4096] row-major
// wg, wu: [4096, 11008] row-major
// ---------------------------------------------------------------------------
__global__ __launch_bounds__(256, 2)
void k_gateup(const float* __restrict__ x,
              const float* __restrict__ wg,
              const float* __restrict__ wu)
{
    const int K = H_DIM;
    const int N = I_DIM;
    const int BM = 128, BN = 64, BK = 16;

    // grouped rasterization: concurrent CTAs share 16 M-tiles (x stays in L2)
    const int num_pid_m = M_DIM / BM;       // 64
    const int num_pid_n = N / BN;           // 172
    const int GROUP_M = 16;
    int pid = blockIdx.x;
    int group_size = GROUP_M * num_pid_n;
    int group_id = pid / group_size;
    int first_pid_m = group_id * GROUP_M;
    int group_m = min(GROUP_M, num_pid_m - first_pid_m);
    int pid_m = first_pid_m + (pid % group_m);
    int pid_n = (pid % group_size) / group_m;

    const int m0 = pid_m * BM;
    const int n0 = pid_n * BN;

    __shared__ float As[2][BK][BM + 4];   // transposed x tile (padded)
    __shared__ float Bg[2][BK][BN];
    __shared__ float Bu[2][BK][BN];

    const int tid = threadIdx.x;
    const int tx = tid & 15;   // 0..15 -> 4 cols each
    const int ty = tid >> 4;   // 0..15 -> 8 rows each

    // global-load assignments
    const int arow = tid >> 2;   // 0..63 (and +64)
    const int ac4  = tid & 3;    // float4 index within 16-wide row
    const int brow = tid >> 4;   // 0..15
    const int bc4  = tid & 15;   // float4 index within 64-wide row

    const float* xrow0 = x + (long long)(m0 + arow) * K + ac4 * 4;
    const float* xrow1 = x + (long long)(m0 + arow + 64) * K + ac4 * 4;

    float4 pa0, pa1, pg4, pu4;

    float accg[8][4];
    float accu[8][4];
#pragma unroll
    for (int i = 0; i < 8; i++)
#pragma unroll
        for (int j = 0; j < 4; j++) { accg[i][j] = 0.f; accu[i][j] = 0.f; }

    const int KT = K / BK;   // 256

    // prologue: load tile 0
    {
        const long long k0 = 0;
        pa0 = *(const float4*)(xrow0 + k0);
        pa1 = *(const float4*)(xrow1 + k0);
        pg4 = *(const float4*)(wg + (k0 + brow) * (long long)N + n0 + bc4 * 4);
        pu4 = *(const float4*)(wu + (k0 + brow) * (long long)N + n0 + bc4 * 4);
        As[0][ac4 * 4 + 0][arow] = pa0.x;
        As[0][ac4 * 4 + 1][arow] = pa0.y;
        As[0][ac4 * 4 + 2][arow] = pa0.z;
        As[0][ac4 * 4 + 3][arow] = pa0.w;
        As[0][ac4 * 4 + 0][arow + 64] = pa1.x;
        As[0][ac4 * 4 + 1][arow + 64] = pa1.y;
        As[0][ac4 * 4 + 2][arow + 64] = pa1.z;
        As[0][ac4 * 4 + 3][arow + 64] = pa1.w;
        *(float4*)&Bg[0][brow][bc4 * 4] = pg4;
        *(float4*)&Bu[0][brow][bc4 * 4] = pu4;
    }
    __syncthreads();

    for (int kt = 0; kt < KT; ++kt) {
        const int cur = kt & 1;
        const int nxt = cur ^ 1;
        if (kt + 1 < KT) {
            const long long k0 = (long long)(kt + 1) * BK;
            pa0 = *(const float4*)(xrow0 + k0);
            pa1 = *(const float4*)(xrow1 + k0);
            pg4 = *(const float4*)(wg + (k0 + brow) * (long long)N + n0 + bc4 * 4);
            pu4 = *(const float4*)(wu + (k0 + brow) * (long long)N + n0 + bc4 * 4);
        }

#pragma unroll
        for (int kk = 0; kk < BK; ++kk) {
            float4 a0 = *(const float4*)&As[cur][kk][ty * 8];
            float4 a1 = *(const float4*)&As[cur][kk][ty * 8 + 4];
            float4 bg = *(const float4*)&Bg[cur][kk][tx * 4];
            float4 bu = *(const float4*)&Bu[cur][kk][tx * 4];
            float a[8] = {a0.x, a0.y, a0.z, a0.w, a1.x, a1.y, a1.z, a1.w};
            float g[4] = {bg.x, bg.y, bg.z, bg.w};
            float u[4] = {bu.x, bu.y, bu.z, bu.w};
#pragma unroll
            for (int i = 0; i < 8; i++) {
#pragma unroll
                for (int j = 0; j < 4; j++) {
                    accg[i][j] = fmaf(a[i], g[j], accg[i][j]);
                    accu[i][j] = fmaf(a[i], u[j], accu[i][j]);
                }
            }
        }

        if (kt + 1 < KT) {
            As[nxt][ac4 * 4 + 0][arow] = pa0.x;
            As[nxt][ac4 * 4 + 1][arow] = pa0.y;
            As[nxt][ac4 * 4 + 2][arow] = pa0.z;
            As[nxt][ac4 * 4 + 3][arow] = pa0.w;
            As[nxt][ac4 * 4 + 0][arow + 64] = pa1.x;
            As[nxt][ac4 * 4 + 1][arow + 64] = pa1.y;
            As[nxt][ac4 * 4 + 2][arow + 64] = pa1.z;
            As[nxt][ac4 * 4 + 3][arow + 64] = pa1.w;
            *(float4*)&Bg[nxt][brow][bc4 * 4] = pg4;
            *(float4*)&Bu[nxt][brow][bc4 * 4] = pu4;
        }
        __syncthreads();
    }

    // epilogue: h = silu(gate) * up
    float* hp = g_h + (long long)m0 * N + n0;
#pragma unroll
    for (int i = 0; i < 8; i++) {
        const int row = ty * 8 + i;
        float4 o;
        float gv, sv;
        gv = accg[i][0]; sv = gv / (1.f + expf(-gv)); o.x = sv * accu[i][0];
        gv = accg[i][1]; sv = gv / (1.f + expf(-gv)); o.y = sv * accu[i][1];
        gv = accg[i][2]; sv = gv / (1.f + expf(-gv)); o.z = sv * accu[i][2];
        gv = accg[i][3]; sv = gv / (1.f + expf(-gv)); o.w = sv * accu[i][3];
        *(float4*)(hp + (long long)row * N + tx * 4) = o;
    }
}

// ---------------------------------------------------------------------------
// Kernel 2: y = h @ w_down
// C tile 128x128, BK=16, 256 threads, 8x8 per thread.
// h: [M, 11008], wd: [11008, 4096], y: [M, 4096]
// ---------------------------------------------------------------------------
__global__ __launch_bounds__(256, 2)
void k_down(const float* __restrict__ wd,
            float* __restrict__ y)
{
    const int K = I_DIM;    // 11008
    const int N = H_DIM;    // 4096
    const int BM = 128, BN = 128, BK = 16;

    const int num_pid_m = M_DIM / BM;   // 64
    const int num_pid_n = N / BN;       // 32
    const int GROUP_M = 8;
    int pid = blockIdx.x;
    int group_size = GROUP_M * num_pid_n;
    int group_id = pid / group_size;
    int first_pid_m = group_id * GROUP_M;
    int group_m = min(GROUP_M, num_pid_m - first_pid_m);
    int pid_m = first_pid_m + (pid % group_m);
    int pid_n = (pid % group_size) / group_m;

    const int m0 = pid_m * BM;
    const int n0 = pid_n * BN;

    __shared__ float As[2][BK][BM + 4];
    __shared__ float Bs[2][BK][BN];

    const int tid = threadIdx.x;
    const int tx = tid & 15;   // 0..15 -> 8 cols each
    const int ty = tid >> 4;   // 0..15 -> 8 rows each

    const int arow = tid >> 2;   // 0..63 (and +64)
    const int ac4  = tid & 3;
    // B tile: 16 rows x 128 cols = 512 float4, 2 per thread
    const int br0 = tid >> 5;          // 0..7  (and +8)
    const int bc4 = tid & 31;          // 0..31

    const float* hrow0 = g_h + (long long)(m0 + arow) * K + ac4 * 4;
    const float* hrow1 = g_h + (long long)(m0 + arow + 64) * K + ac4 * 4;

    float4 pa0, pa1, pb0, pb1;

    float acc[8][8];
#pragma unroll
    for (int i = 0; i < 8; i++)
#pragma unroll
        for (int j = 0; j < 8; j++) acc[i][j] = 0.f;

    const int KT = K / BK;   // 688

    {
        const long long k0 = 0;
        pa0 = *(const float4*)(hrow0 + k0);
        pa1 = *(const float4*)(hrow1 + k0);
        pb0 = *(const float4*)(wd + (k0 + br0) * (long long)N + n0 + bc4 * 4);
        pb1 = *(const float4*)(wd + (k0 + br0 + 8) * (long long)N + n0 + bc4 * 4);
        As[0][ac4 * 4 + 0][arow] = pa0.x;
        As[0][ac4 * 4 + 1][arow] = pa0.y;
        As[0][ac4 * 4 + 2][arow] = pa0.z;
        As[0][ac4 * 4 + 3][arow] = pa0.w;
        As[0][ac4 * 4 + 0][arow + 64] = pa1.x;
        As[0][ac4 * 4 + 1][arow + 64] = pa1.y;
        As[0][ac4 * 4 + 2][arow + 64] = pa1.z;
        As[0][ac4 * 4 + 3][arow + 64] = pa1.w;
        *(float4*)&Bs[0][br0][bc4 * 4] = pb0;
        *(float4*)&Bs[0][br0 + 8][bc4 * 4] = pb1;
    }
    __syncthreads();

    for (int kt = 0; kt < KT; ++kt) {
        const int cur = kt & 1;
        const int nxt = cur ^ 1;
        if (kt + 1 < KT) {
            const long long k0 = (long long)(kt + 1) * BK;
            pa0 = *(const float4*)(hrow0 + k0);
            pa1 = *(const float4*)(hrow1 + k0);
            pb0 = *(const float4*)(wd + (k0 + br0) * (long long)N + n0 + bc4 * 4);
            pb1 = *(const float4*)(wd + (k0 + br0 + 8) * (long long)N + n0 + bc4 * 4);
        }

#pragma unroll
        for (int kk = 0; kk < BK; ++kk) {
            float4 a0 = *(const float4*)&As[cur][kk][ty * 8];
            float4 a1 = *(const float4*)&As[cur][kk][ty * 8 + 4];
            float4 b0 = *(const float4*)&Bs[cur][kk][tx * 8];
            float4 b1 = *(const float4*)&Bs[cur][kk][tx * 8 + 4];
            float a[8] = {a0.x, a0.y, a0.z, a0.w, a1.x, a1.y, a1.z, a1.w};
            float b[8] = {b0.x, b0.y, b0.z, b0.w, b1.x, b1.y, b1.z, b1.w};
#pragma unroll
            for (int i = 0; i < 8; i++) {
#pragma unroll
                for (int j = 0; j < 8; j++) {
                    acc[i][j] = fmaf(a[i], b[j], acc[i][j]);
                }
            }
        }

        if (kt + 1 < KT) {
            As[nxt][ac4 * 4 + 0][arow] = pa0.x;
            As[nxt][ac4 * 4 + 1][arow] = pa0.y;
            As[nxt][ac4 * 4 + 2][arow] = pa0.z;
            As[nxt][ac4 * 4 + 3][arow] = pa0.w;
            As[nxt][ac4 * 4 + 0][arow + 64] = pa1.x;
            As[nxt][ac4 * 4 + 1][arow + 64] = pa1.y;
            As[nxt][ac4 * 4 + 2][arow + 64] = pa1.z;
            As[nxt][ac4 * 4 + 3][arow + 64] = pa1.w;
            *(float4*)&Bs[nxt][br0][bc4 * 4] = pb0;
            *(float4*)&Bs[nxt][br0 + 8][bc4 * 4] = pb1;
        }
        __syncthreads();
    }

    float* yp = y + (long long)m0 * N + n0;
#pragma unroll
    for (int i = 0; i < 8; i++) {
        const int row = ty * 8 + i;
        float4 o0, o1;
        o0.x = acc[i][0]; o0.y = acc[i][1]; o0.z = acc[i][2]; o0.w = acc[i][3];
        o1.x = acc[i][4]; o1.y = acc[i][5]; o1.z = acc[i][6]; o1.w = acc[i][7];
        *(float4*)(yp + (long long)row * N + tx * 8) = o0;
        *(float4*)(yp + (long long)row * N + tx * 8 + 4) = o1;
    }
}

// ---------------------------------------------------------------------------
extern "C" void kernel_launch(void* const* d_in, const int* in_sizes, int n_in,
                              void* d_out, int out_size)
{
    const float* x  = (const float*)d_in[0];
    const float* wg = (const float*)d_in[1];
    const float* wu = (const float*)d_in[2];
    const float* wd = (const float*)d_in[3];
    float* y = (float*)d_out;

    const int grid1 = (M_DIM / 128) * (I_DIM / 64);    // 64 * 172 = 11008
    const int grid2 = (M_DIM / 128) * (H_DIM / 128);   // 64 * 32  = 2048

    k_gateup<<<grid1, 256>>>(x, wg, wu);
    k_down<<<grid2, 256>>>(wd, y);
}

// round 4
// speedup vs baseline: 2.4522x; 2.4522x over previous
#include <cuda_runtime.h>
#include <cuda_bf16.h>
#include <math.h>
#include <stdint.h>

#define M_DIM 8192
#define H_DIM 4096
#define I_DIM 11008

// Intermediate h = silu(x@wg)*(x@wu), pre-split bf16 hi/lo  [M, I] each
__device__ unsigned short g_h_hi[(size_t)M_DIM * I_DIM];
__device__ unsigned short g_h_lo[(size_t)M_DIM * I_DIM];

__device__ __forceinline__ uint32_t smem_u32(const void* p) {
    uint32_t a;
    asm("{ .reg .u64 t; cvta.to.shared.u64 t, %1; cvt.u32.u64 %0, t; }" : "=r"(a) : "l"(p));
    return a;
}
__device__ __forceinline__ uint32_t pack_bf2(float a, float b) {
    uint32_t r;
    asm("cvt.rn.bf16x2.f32 %0, %1, %2;" : "=r"(r) : "f"(b), "f"(a));
    return r;
}
// split pair (a,b) -> hi bf16x2 (low half = a), lo bf16x2 (residual)
__device__ __forceinline__ void split2(float a, float b, uint32_t& hi, uint32_t& lo) {
    hi = pack_bf2(a, b);
    lo = pack_bf2(a - __uint_as_float(hi << 16), b - __uint_as_float(hi & 0xFFFF0000u));
}
__device__ __forceinline__ void ldsm4(uint32_t* r, uint32_t addr) {
    asm volatile("ldmatrix.sync.aligned.m8n8.x4.shared.b16 {%0,%1,%2,%3}, [%4];"
                 : "=r"(r[0]), "=r"(r[1]), "=r"(r[2]), "=r"(r[3]) : "r"(addr));
}
__device__ __forceinline__ void mma16816(float* c, const uint32_t* a, uint32_t b0, uint32_t b1) {
    asm volatile(
        "mma.sync.aligned.m16n8k16.row.col.f32.bf16.bf16.f32 "
        "{%0,%1,%2,%3}, {%4,%5,%6,%7}, {%8,%9}, {%0,%1,%2,%3};"
        : "+f"(c[0]), "+f"(c[1]), "+f"(c[2]), "+f"(c[3])
        : "r"(a[0]), "r"(a[1]), "r"(a[2]), "r"(a[3]), "r"(b0), "r"(b1));
}

// smem: row stride 40 bf16 = 80B (conflict-free for ldmatrix 16B row fetches)
// GEMM1 per-stage 40960B: A_hi 0, A_lo 10240, G_hi 20480, G_lo 25600, U_hi 30720, U_lo 35840
// GEMM2 per-stage 40960B: A_hi 0, A_lo 10240, B_hi 20480, B_lo 30720
#define STAGE 40960
#define SMEM_BYTES (2 * STAGE)

// ---------------------------------------------------------------------------
// GEMM1: h = silu(x@wg) * (x@wu).  CTA tile: 128(M) x 64(N per matrix), BK=32.
// 256 threads, warps 4(M) x 2(N); warp tile 32x32 per matrix.
// ---------------------------------------------------------------------------
__global__ __launch_bounds__(256, 1)
void k_gateup(const float* __restrict__ x,
              const float* __restrict__ wg,
              const float* __restrict__ wu)
{
    extern __shared__ char smp[];
    const uint32_t sbase = smem_u32(smp);

    const int t = threadIdx.x, lane = t & 31, wid = t >> 5;
    const int wm = wid & 3, wn = wid >> 2;

    const int num_pid_m = M_DIM / 128, num_pid_n = I_DIM / 64, GROUP = 16;
    int pid = blockIdx.x;
    int gsz = GROUP * num_pid_n;
    int gid = pid / gsz;
    int first = gid * GROUP;
    int gm = min(GROUP, num_pid_m - first);
    int pid_m = first + (pid % gm);
    int pid_n = (pid % gsz) / gm;
    const int m0 = pid_m * 128, n0 = pid_n * 64;

    float accg[2][4][4];
    float accu[2][4][4];
#pragma unroll
    for (int i = 0; i < 2; i++)
#pragma unroll
        for (int j = 0; j < 4; j++)
#pragma unroll
            for (int k = 0; k < 4; k++) { accg[i][j][k] = 0.f; accu[i][j][k] = 0.f; }

    const int KT = H_DIM / 32;   // 128

    float4 pa[4];
    float  pb[4][4];

    auto gload = [&](int kt) {
        const float* xs = x + (long long)m0 * H_DIM + kt * 32;
#pragma unroll
        for (int j = 0; j < 4; j++) {
            int idx = j * 256 + t, row = idx >> 3, c4 = idx & 7;
            pa[j] = *(const float4*)(xs + (long long)row * H_DIM + c4 * 4);
        }
#pragma unroll
        for (int j = 0; j < 4; j++) {
            int task = j * 256 + t;
            const float* W = (task < 512) ? wg : wu;
            int rem = task & 511, kq = rem >> 6, n = rem & 63;
            const float* s = W + (long long)(kt * 32 + kq * 4) * I_DIM + n0 + n;
            pb[j][0] = s[0]; pb[j][1] = s[I_DIM]; pb[j][2] = s[2 * I_DIM]; pb[j][3] = s[3 * I_DIM];
        }
    };
    auto sstore = [&](int st) {
        char* sp = smp + st * STAGE;
#pragma unroll
        for (int j = 0; j < 4; j++) {
            int idx = j * 256 + t, row = idx >> 3, c4 = idx & 7;
            uint32_t h0, l0, h1, l1;
            split2(pa[j].x, pa[j].y, h0, l0);
            split2(pa[j].z, pa[j].w, h1, l1);
            int off = row * 80 + c4 * 8;
            *(uint2*)(sp + off)         = make_uint2(h0, h1);
            *(uint2*)(sp + 10240 + off) = make_uint2(l0, l1);
        }
#pragma unroll
        for (int j = 0; j < 4; j++) {
            int task = j * 256 + t;
            int base = (task < 512) ? 20480 : 30720;
            int rem = task & 511, kq = rem >> 6, n = rem & 63;
            uint32_t h0, l0, h1, l1;
            split2(pb[j][0], pb[j][1], h0, l0);
            split2(pb[j][2], pb[j][3], h1, l1);
            int off = n * 80 + kq * 8;
            *(uint2*)(sp + base + off)        = make_uint2(h0, h1);
            *(uint2*)(sp + base + 5120 + off) = make_uint2(l0, l1);
        }
    };

    // ldmatrix lane addressing
    const uint32_t a_row  = (uint32_t)(lane & 15);
    const uint32_t a_koff = (uint32_t)((lane >> 4) * 8);
    const uint32_t b_n    = (uint32_t)((lane & 7) + ((lane >> 4) << 3));
    const uint32_t b_koff = (uint32_t)(((lane >> 3) & 1) * 8);

    gload(0);
    sstore(0);
    __syncthreads();

    for (int kt = 0; kt < KT; ++kt) {
        const int cur = kt & 1;
        if (kt + 1 < KT) gload(kt + 1);

        const uint32_t sA = sbase + (uint32_t)cur * STAGE;
#pragma unroll
        for (int ks = 0; ks < 2; ks++) {
            uint32_t ah[2][4], al[2][4];
#pragma unroll
            for (int mt = 0; mt < 2; mt++) {
                uint32_t addr = sA + (uint32_t)((wm * 32 + mt * 16 + a_row) * 80) + (uint32_t)(ks * 32) + a_koff * 2;
                ldsm4(ah[mt], addr);
                ldsm4(al[mt], addr + 10240);
            }
            // gate
            {
                uint32_t bh[2][4], bl[2][4];
#pragma unroll
                for (int blk = 0; blk < 2; blk++) {
                    uint32_t addr = sA + 20480u + (uint32_t)((wn * 32 + blk * 16 + b_n) * 80) + (uint32_t)(ks * 32) + b_koff * 2;
                    ldsm4(bh[blk], addr);
                    ldsm4(bl[blk], addr + 5120);
                }
#pragma unroll
                for (int mt = 0; mt < 2; mt++)
#pragma unroll
                    for (int n8 = 0; n8 < 4; n8++) {
                        int blk = n8 >> 1, h = (n8 & 1) * 2;
                        mma16816(accg[mt][n8], ah[mt], bh[blk][h], bh[blk][h + 1]);
                        mma16816(accg[mt][n8], ah[mt], bl[blk][h], bl[blk][h + 1]);
                        mma16816(accg[mt][n8], al[mt], bh[blk][h], bh[blk][h + 1]);
                    }
            }
            // up
            {
                uint32_t bh[2][4], bl[2][4];
#pragma unroll
                for (int blk = 0; blk < 2; blk++) {
                    uint32_t addr = sA + 30720u + (uint32_t)((wn * 32 + blk * 16 + b_n) * 80) + (uint32_t)(ks * 32) + b_koff * 2;
                    ldsm4(bh[blk], addr);
                    ldsm4(bl[blk], addr + 5120);
                }
#pragma unroll
                for (int mt = 0; mt < 2; mt++)
#pragma unroll
                    for (int n8 = 0; n8 < 4; n8++) {
                        int blk = n8 >> 1, h = (n8 & 1) * 2;
                        mma16816(accu[mt][n8], ah[mt], bh[blk][h], bh[blk][h + 1]);
                        mma16816(accu[mt][n8], ah[mt], bl[blk][h], bl[blk][h + 1]);
                        mma16816(accu[mt][n8], al[mt], bh[blk][h], bh[blk][h + 1]);
                    }
            }
        }

        if (kt + 1 < KT) sstore(cur ^ 1);
        __syncthreads();
    }

    // epilogue: h = silu(g)*u, split to bf16 hi/lo
#pragma unroll
    for (int mt = 0; mt < 2; mt++) {
#pragma unroll
        for (int n8 = 0; n8 < 4; n8++) {
            int row = m0 + wm * 32 + mt * 16 + (lane >> 2);
            int col = n0 + wn * 32 + n8 * 8 + (lane & 3) * 2;
#pragma unroll
            for (int half = 0; half < 2; half++) {
                int r = row + half * 8;
                float g0 = accg[mt][n8][half * 2],     u0 = accu[mt][n8][half * 2];
                float g1 = accg[mt][n8][half * 2 + 1], u1 = accu[mt][n8][half * 2 + 1];
                float h0 = g0 / (1.f + __expf(-g0)) * u0;
                float h1 = g1 / (1.f + __expf(-g1)) * u1;
                uint32_t hi, lo;
                split2(h0, h1, hi, lo);
                long long idx = (long long)r * I_DIM + col;
                *(uint32_t*)&g_h_hi[idx] = hi;
                *(uint32_t*)&g_h_lo[idx] = lo;
            }
        }
    }
}

// ---------------------------------------------------------------------------
// GEMM2: y = h @ wd.  CTA tile 128 x 128, BK=32. Warp tile 32 x 64.
// ---------------------------------------------------------------------------
__global__ __launch_bounds__(256, 1)
void k_down(const float* __restrict__ wd, float* __restrict__ y)
{
    extern __shared__ char smp[];
    const uint32_t sbase = smem_u32(smp);

    const int t = threadIdx.x, lane = t & 31, wid = t >> 5;
    const int wm = wid & 3, wn = wid >> 2;

    const int num_pid_m = M_DIM / 128, num_pid_n = H_DIM / 128, GROUP = 8;
    int pid = blockIdx.x;
    int gsz = GROUP * num_pid_n;
    int gid = pid / gsz;
    int first = gid * GROUP;
    int gm = min(GROUP, num_pid_m - first);
    int pid_m = first + (pid % gm);
    int pid_n = (pid % gsz) / gm;
    const int m0 = pid_m * 128, n0 = pid_n * 128;

    float acc[2][8][4];
#pragma unroll
    for (int i = 0; i < 2; i++)
#pragma unroll
        for (int j = 0; j < 8; j++)
#pragma unroll
            for (int k = 0; k < 4; k++) acc[i][j][k] = 0.f;

    const int KT = I_DIM / 32;   // 344

    uint4 pa[4];
    float pb[4][4];

    auto gload = [&](int kt) {
#pragma unroll
        for (int j = 0; j < 4; j++) {
            int idx = j * 256 + t, arr = idx >> 9, rem = idx & 511;
            int row = rem >> 2, c8 = rem & 3;
            const unsigned short* hp = arr ? g_h_lo : g_h_hi;
            pa[j] = *(const uint4*)(hp + (long long)(m0 + row) * I_DIM + kt * 32 + c8 * 8);
        }
#pragma unroll
        for (int j = 0; j < 4; j++) {
            int idx = j * 256 + t, kq = idx >> 7, n = idx & 127;
            const float* s = wd + (long long)(kt * 32 + kq * 4) * H_DIM + n0 + n;
            pb[j][0] = s[0]; pb[j][1] = s[H_DIM]; pb[j][2] = s[2 * H_DIM]; pb[j][3] = s[3 * H_DIM];
        }
    };
    auto sstore = [&](int st) {
        char* sp = smp + st * STAGE;
#pragma unroll
        for (int j = 0; j < 4; j++) {
            int idx = j * 256 + t, arr = idx >> 9, rem = idx & 511;
            int row = rem >> 2, c8 = rem & 3;
            *(uint4*)(sp + arr * 10240 + row * 80 + c8 * 16) = pa[j];
        }
#pragma unroll
        for (int j = 0; j < 4; j++) {
            int idx = j * 256 + t, kq = idx >> 7, n = idx & 127;
            uint32_t h0, l0, h1, l1;
            split2(pb[j][0], pb[j][1], h0, l0);
            split2(pb[j][2], pb[j][3], h1, l1);
            int off = n * 80 + kq * 8;
            *(uint2*)(sp + 20480 + off) = make_uint2(h0, h1);
            *(uint2*)(sp + 30720 + off) = make_uint2(l0, l1);
        }
    };

    const uint32_t a_row  = (uint32_t)(lane & 15);
    const uint32_t a_koff = (uint32_t)((lane >> 4) * 8);
    const uint32_t b_n    = (uint32_t)((lane & 7) + ((lane >> 4) << 3));
    const uint32_t b_koff = (uint32_t)(((lane >> 3) & 1) * 8);

    gload(0);
    sstore(0);
    __syncthreads();

    for (int kt = 0; kt < KT; ++kt) {
        const int cur = kt & 1;
        if (kt + 1 < KT) gload(kt + 1);

        const uint32_t sA = sbase + (uint32_t)cur * STAGE;
#pragma unroll
        for (int ks = 0; ks < 2; ks++) {
            uint32_t ah[2][4], al[2][4];
#pragma unroll
            for (int mt = 0; mt < 2; mt++) {
                uint32_t addr = sA + (uint32_t)((wm * 32 + mt * 16 + a_row) * 80) + (uint32_t)(ks * 32) + a_koff * 2;
                ldsm4(ah[mt], addr);
                ldsm4(al[mt], addr + 10240);
            }
            // process 4 n16 blocks in halves of 2 to cap register pressure
#pragma unroll
            for (int half = 0; half < 2; half++) {
                uint32_t bh[2][4], bl[2][4];
#pragma unroll
                for (int b = 0; b < 2; b++) {
                    int blk = half * 2 + b;
                    uint32_t addr = sA + 20480u + (uint32_t)((wn * 64 + blk * 16 + b_n) * 80) + (uint32_t)(ks * 32) + b_koff * 2;
                    ldsm4(bh[b], addr);
                    ldsm4(bl[b], addr + 10240);
                }
#pragma unroll
                for (int mt = 0; mt < 2; mt++)
#pragma unroll
                    for (int q = 0; q < 4; q++) {
                        int n8 = half * 4 + q;
                        int b = q >> 1, h = (q & 1) * 2;
                        mma16816(acc[mt][n8], ah[mt], bh[b][h], bh[b][h + 1]);
                        mma16816(acc[mt][n8], ah[mt], bl[b][h], bl[b][h + 1]);
                        mma16816(acc[mt][n8], al[mt], bh[b][h], bh[b][h + 1]);
                    }
            }
        }

        if (kt + 1 < KT) sstore(cur ^ 1);
        __syncthreads();
    }

#pragma unroll
    for (int mt = 0; mt < 2; mt++) {
#pragma unroll
        for (int n8 = 0; n8 < 8; n8++) {
            int row = m0 + wm * 32 + mt * 16 + (lane >> 2);
            int col = n0 + wn * 64 + n8 * 8 + (lane & 3) * 2;
#pragma unroll
            for (int half = 0; half < 2; half++) {
                int r = row + half * 8;
                float2 o = make_float2(acc[mt][n8][half * 2], acc[mt][n8][half * 2 + 1]);
                *(float2*)(y + (long long)r * H_DIM + col) = o;
            }
        }
    }
}

// ---------------------------------------------------------------------------
extern "C" void kernel_launch(void* const* d_in, const int* in_sizes, int n_in,
                              void* d_out, int out_size)
{
    const float* x  = (const float*)d_in[0];
    const float* wg = (const float*)d_in[1];
    const float* wu = (const float*)d_in[2];
    const float* wd = (const float*)d_in[3];
    float* y = (float*)d_out;

    static int configured = 0;
    cudaFuncSetAttribute(k_gateup, cudaFuncAttributeMaxDynamicSharedMemorySize, SMEM_BYTES);
    cudaFuncSetAttribute(k_down,   cudaFuncAttributeMaxDynamicSharedMemorySize, SMEM_BYTES);
    (void)configured;

    const int grid1 = (M_DIM / 128) * (I_DIM / 64);    // 11008
    const int grid2 = (M_DIM / 128) * (H_DIM / 128);   // 2048

    k_gateup<<<grid1, 256, SMEM_BYTES>>>(x, wg, wu);
    k_down<<<grid2, 256, SMEM_BYTES>>>(wd, y);
}